// round 9
// baseline (speedup 1.0000x reference)
#include <cuda_runtime.h>
#include <cuda_bf16.h>
#include <math.h>

// Problem constants
#define B_   64
#define L_   512
#define D_   256
#define H_   256
#define T_   11
#define M_   (B_ * L_)      // 32768 rows (b*L + l)
#define G4H  (4 * H_)       // 1024 gate rows (i,f,g,o blocks of 256)

#define NBLK_LSTM 128       // persistent blocks (<=148 SMs, 1/SM)

typedef unsigned long long ull_t;

// Packed fp32x2 FMA: d = a*b + c elementwise on 2 packed floats (sm_100+)
__device__ __forceinline__ ull_t ffma2(ull_t a, ull_t b, ull_t c) {
    ull_t d;
    asm("fma.rn.f32x2 %0, %1, %2, %3;" : "=l"(d) : "l"(a), "l"(b), "l"(c));
    return d;
}
__device__ __forceinline__ float pair_sum(ull_t v) {
    float2 f = *(float2*)&v;
    return f.x + f.y;
}

// ---------------------------------------------------------------------------
// Scratch (static __device__ — no allocations allowed)
// ---------------------------------------------------------------------------
__device__ float g_gates[2 * 32768 * 1024];     // [dir][b*L+l][4H] input-proj + bias
__device__ float g_hseq[32768 * 512];           // [b*L+l][512] = concat(hf, hb)
__device__ float g_hbuf[2][2][B_ * H_];         // [dir][parity][b*H + j]
__device__ float g_logits[32768 * T_];          // [b*L+l][T]
__device__ unsigned int g_cnt[2][8];            // per-(dir, batch-group) completion count

// ---------------------------------------------------------------------------
// Init: copy h0 into parity-0 h buffers, reset counters
// ---------------------------------------------------------------------------
__global__ void init_kernel(const float* __restrict__ h0) {
    int i = blockIdx.x * blockDim.x + threadIdx.x;
    if (i < 16) ((unsigned int*)g_cnt)[i] = 0u;
    if (i < 2 * B_ * H_) {
        int dir = i / (B_ * H_);
        int rem = i - dir * (B_ * H_);
        g_hbuf[dir][0][rem] = h0[i];
    }
}

// ---------------------------------------------------------------------------
// Fused embedding-gather + input GEMM (fp32x2 packed along k):
//   g_gates[dir][m][n] = emb[sent[m]] . W_ih_dir[n] + b_dir[n]
// M=32768, N=1024, K=256.
// 128x64 block tile, 256 threads, 8x4 per thread, k-chunk 16,
// double-buffered smem stored k-pair-interleaved: As2[k/2][m] = (a_k, a_k+1).
// Inner product uses fma.rn.f32x2: 1 issue = 2 fp32 FMA lanes.
// ---------------------------------------------------------------------------
__global__ __launch_bounds__(256) void input_gemm_kernel(
    const int* __restrict__ sent, const float* __restrict__ emb,
    const float* __restrict__ Wf, const float* __restrict__ bf,
    const float* __restrict__ Wb, const float* __restrict__ bb)
{
    __shared__ float2 As2[2][8][132];   // [buf][k2][m]
    __shared__ float2 Bs2[2][8][68];    // [buf][k2][n]
    __shared__ int    sidx[128];

    const int dir = blockIdx.z;
    const float* W    = dir ? Wb : Wf;
    const float* bias = dir ? bb : bf;
    float* out = g_gates + (size_t)dir * M_ * G4H;

    const int n0 = blockIdx.x * 64;
    const int m0 = blockIdx.y * 128;
    const int tid = threadIdx.x;

    if (tid < 128) sidx[tid] = sent[m0 + tid];
    __syncthreads();

    // Global-load mapping
    const int rowA = tid >> 1;              // 0..127
    const int kA0  = (tid & 1) * 8;         // 0 or 8 (loads kA0..kA0+7)
    const int kA2  = kA0 >> 1;              // k2 base 0 or 4
    const int rowB = tid >> 2;              // 0..63
    const int kB0  = (tid & 3) * 4;         // 0,4,8,12
    const int kB2  = kB0 >> 1;              // k2 base 0,2,4,6
    const float* aBase = emb + (size_t)sidx[rowA] * D_ + kA0;
    const float* bBase = W   + (size_t)(n0 + rowB) * D_ + kB0;

    // Compute mapping: 8 rows x 4 cols per thread
    const int txn = tid & 15;               // n-quad 0..15
    const int tym = tid >> 4;               // m-oct 0..15

    ull_t acc2[8][4];
#pragma unroll
    for (int i = 0; i < 8; i++)
#pragma unroll
        for (int j = 0; j < 4; j++) acc2[i][j] = 0ull;

    float4 pa0, pa1, pb;

    // Preload chunk 0 into buf 0
    pa0 = *(const float4*)(aBase + 0);
    pa1 = *(const float4*)(aBase + 4);
    pb  = *(const float4*)(bBase + 0);
    As2[0][kA2 + 0][rowA] = make_float2(pa0.x, pa0.y);
    As2[0][kA2 + 1][rowA] = make_float2(pa0.z, pa0.w);
    As2[0][kA2 + 2][rowA] = make_float2(pa1.x, pa1.y);
    As2[0][kA2 + 3][rowA] = make_float2(pa1.z, pa1.w);
    Bs2[0][kB2 + 0][rowB] = make_float2(pb.x, pb.y);
    Bs2[0][kB2 + 1][rowB] = make_float2(pb.z, pb.w);
    __syncthreads();

    for (int c = 0; c < 16; c++) {
        const int cur = c & 1;
        if (c < 15) {                       // prefetch next chunk into regs
            const float* ap = aBase + (c + 1) * 16;
            const float* bp = bBase + (c + 1) * 16;
            pa0 = *(const float4*)(ap + 0);
            pa1 = *(const float4*)(ap + 4);
            pb  = *(const float4*)(bp + 0);
        }
#pragma unroll
        for (int kk2 = 0; kk2 < 8; kk2++) {
            ulonglong2 a01 = *(const ulonglong2*)&As2[cur][kk2][tym * 8 + 0];
            ulonglong2 a23 = *(const ulonglong2*)&As2[cur][kk2][tym * 8 + 2];
            ulonglong2 a45 = *(const ulonglong2*)&As2[cur][kk2][tym * 8 + 4];
            ulonglong2 a67 = *(const ulonglong2*)&As2[cur][kk2][tym * 8 + 6];
            ulonglong2 b01 = *(const ulonglong2*)&Bs2[cur][kk2][txn * 4 + 0];
            ulonglong2 b23 = *(const ulonglong2*)&Bs2[cur][kk2][txn * 4 + 2];
            ull_t av[8] = {a01.x, a01.y, a23.x, a23.y, a45.x, a45.y, a67.x, a67.y};
            ull_t bv[4] = {b01.x, b01.y, b23.x, b23.y};
#pragma unroll
            for (int i = 0; i < 8; i++)
#pragma unroll
                for (int j = 0; j < 4; j++)
                    acc2[i][j] = ffma2(av[i], bv[j], acc2[i][j]);
        }
        if (c < 15) {
            const int nxt = cur ^ 1;
            As2[nxt][kA2 + 0][rowA] = make_float2(pa0.x, pa0.y);
            As2[nxt][kA2 + 1][rowA] = make_float2(pa0.z, pa0.w);
            As2[nxt][kA2 + 2][rowA] = make_float2(pa1.x, pa1.y);
            As2[nxt][kA2 + 3][rowA] = make_float2(pa1.z, pa1.w);
            Bs2[nxt][kB2 + 0][rowB] = make_float2(pb.x, pb.y);
            Bs2[nxt][kB2 + 1][rowB] = make_float2(pb.z, pb.w);
        }
        __syncthreads();
    }

    const int nbase = n0 + txn * 4;
    float4 bv4 = *(const float4*)&bias[nbase];
#pragma unroll
    for (int i = 0; i < 8; i++) {
        int m = m0 + tym * 8 + i;
        float4 o;
        o.x = pair_sum(acc2[i][0]) + bv4.x;
        o.y = pair_sum(acc2[i][1]) + bv4.y;
        o.z = pair_sum(acc2[i][2]) + bv4.z;
        o.w = pair_sum(acc2[i][3]) + bv4.w;
        *(float4*)&out[(size_t)m * G4H + nbase] = o;
    }
}

// ---------------------------------------------------------------------------
// Persistent BiLSTM recurrence — R7 256-thread layout + fp32x2 inner product.
// 128 blocks: dir = bid>>6; block owns 8 batches (bg) x 32 hidden units (j0).
// Sync: per-(dir,bg) monotonic counter; consumer needs only its 8 producers.
//
// GEMM: ks = tid&7 (8-way interleaved k-split), tile = tid>>3:
// rt = tile>>1 (8-row group), bq = tile&1 (4-batch group).
// Each thread: 8 rows x 4 batches x 32 k -> 512 FFMA2, 96 LDS.128.
// Accumulators are f32x2 pairs (k-even/k-odd), summed before the
// 3-round shuffle butterfly reduction over ks.
// ---------------------------------------------------------------------------
__global__ __launch_bounds__(256, 1) void lstm_kernel(
    const float* __restrict__ c0,
    const float* __restrict__ Whh_f, const float* __restrict__ Whh_b)
{
    extern __shared__ float sm[];
    float4* Wsm4 = (float4*)sm;                    // 128 rows * 65 float4 (pad)
    float4* hsm4 = (float4*)(sm + 128 * 260);      // 8 batches * 65 float4
    float*  Gsm  = sm + 128 * 260 + 8 * 260;       // 128 rows * 9 (pad)

    const int tid = threadIdx.x;
    const int bid = blockIdx.x;
    const int dir = bid >> 6;
    const int sub = bid & 63;
    const int bg  = sub >> 3;              // batch group 0..7
    const int b0  = bg * 8;                // batch tile base
    const int j0  = (sub & 7) * 32;        // hidden tile base

    // Load W_hh slice once: smem row r -> gate g=r>>5, unit j0+(r&31)
    const float4* Wg4 = (const float4*)(dir ? Whh_b : Whh_f);
    for (int idx = tid; idx < 128 * 64; idx += 256) {
        int r = idx >> 6, k4 = idx & 63;
        int g = r >> 5, jj = r & 31;
        Wsm4[r * 65 + k4] = Wg4[(size_t)(g * H_ + j0 + jj) * 64 + k4];
    }

    // Cell-update thread mapping
    const int ub = tid >> 5, ujj = tid & 31;
    float c = c0[dir * B_ * H_ + (b0 + ub) * H_ + j0 + ujj];

    // GEMM thread mapping
    const int ks   = tid & 7;
    const int tile = tid >> 3;
    const int rt   = tile >> 1;            // 0..15 -> rows rt*8..rt*8+7
    const int bq   = tile & 1;             // batches bq*4..bq*4+3
    const int ri_fin = ((ks & 1) << 2) | (ks & 2) | ((ks >> 2) & 1);
    const int row_fin = rt * 8 + ri_fin;
    const int grow_fin = (row_fin >> 5) * H_ + j0 + (row_fin & 31);

    const float* gatesD = g_gates + (size_t)dir * M_ * G4H;
    volatile unsigned int* cnt = &g_cnt[dir][bg];

    __syncthreads();

    for (int t = 0; t < L_; t++) {
        const int l  = dir ? (L_ - 1 - t) : t;
        const float* hread  = g_hbuf[dir][t & 1];
        float*       hwrite = g_hbuf[dir][(t & 1) ^ 1];

        // Prefetch input-projection preacts — in flight during producer wait
        float gi[4];
#pragma unroll
        for (int bi = 0; bi < 4; bi++)
            gi[bi] = gatesD[(size_t)((b0 + bq * 4 + bi) * L_ + l) * G4H + grow_fin];

        // Wait for the 8 producers of this batch group (prev step published)
        if (t > 0) {
            const unsigned int need = 8u * (unsigned)t;
            while (*cnt < need) { __nanosleep(20); }
        }

        // Stage previous h (8 batches x 256 units); L2-coherent loads
        const float4* hr4 = (const float4*)hread;
        for (int i = tid; i < 8 * 64; i += 256) {
            int r = i >> 6, c4 = i & 63;
            hsm4[r * 65 + c4] = __ldcg(&hr4[(b0 + r) * 64 + c4]);
        }
        __syncthreads();

        // 8x4 register-tiled GEMM (f32x2 pairs), interleaved k-split
        ull_t acc2[32];
#pragma unroll
        for (int v = 0; v < 32; v++) acc2[v] = 0ull;

#pragma unroll 2
        for (int kk = 0; kk < 8; kk++) {
            const int k4 = ks + kk * 8;
            ulonglong2 hv[4];
#pragma unroll
            for (int bi = 0; bi < 4; bi++)
                hv[bi] = *(const ulonglong2*)&hsm4[(bq * 4 + bi) * 65 + k4];
#pragma unroll
            for (int ri = 0; ri < 8; ri++) {
                ulonglong2 w = *(const ulonglong2*)&Wsm4[(rt * 8 + ri) * 65 + k4];
#pragma unroll
                for (int bi = 0; bi < 4; bi++) {
                    ull_t a = acc2[ri * 4 + bi];
                    a = ffma2(w.x, hv[bi].x, a);
                    a = ffma2(w.y, hv[bi].y, a);
                    acc2[ri * 4 + bi] = a;
                }
            }
        }

        // Horizontal pair sums -> scalar partials
        float acc[32];
#pragma unroll
        for (int v = 0; v < 32; v++) acc[v] = pair_sum(acc2[v]);

        // K-split reduction: 3 butterfly rounds over lane bits 0..2 (ks)
#pragma unroll
        for (int s = 0; s < 3; s++) {
            const int half = 16 >> s;              // 16, 8, 4
            const bool up = (ks >> s) & 1;
#pragma unroll
            for (int i = 0; i < half; i++) {
                float send = up ? acc[i] : acc[i + half];
                float recv = __shfl_xor_sync(0xffffffffu, send, 1 << s);
                acc[i] = (up ? acc[i + half] : acc[i]) + recv;
            }
        }
#pragma unroll
        for (int bi = 0; bi < 4; bi++)
            Gsm[row_fin * 9 + bq * 4 + bi] = acc[bi] + gi[bi];
        __syncthreads();

        // Gate nonlinearity + state update (PyTorch order i,f,g,o)
        float iv = Gsm[( 0 + ujj) * 9 + ub];
        float fv = Gsm[(32 + ujj) * 9 + ub];
        float gv = Gsm[(64 + ujj) * 9 + ub];
        float ov = Gsm[(96 + ujj) * 9 + ub];
        float si = 1.f / (1.f + expf(-iv));
        float sf = 1.f / (1.f + expf(-fv));
        float so = 1.f / (1.f + expf(-ov));
        c = sf * c + si * tanhf(gv);
        float h = so * tanhf(c);

        int bglob = b0 + ub;
        __stcg(&hwrite[bglob * H_ + j0 + ujj], h);
        __stcg(&g_hseq[(size_t)(bglob * L_ + l) * 512 + dir * H_ + j0 + ujj], h);

        // Publish: all h stores done -> bump group counter
        __syncthreads();
        if (tid == 0) {
            __threadfence();
            atomicAdd(&g_cnt[dir][bg], 1u);
        }
    }
}

// ---------------------------------------------------------------------------
// Output projection: logits[m][t] = hseq[m] . W_out[t] + b_out[t]
// ---------------------------------------------------------------------------
__global__ __launch_bounds__(256) void logits_kernel(
    const float* __restrict__ Wout, const float* __restrict__ bout)
{
    __shared__ float Wo[T_ * 512];
    __shared__ float bo[T_];
    int tid = threadIdx.x;
    for (int i = tid; i < T_ * 512; i += 256) Wo[i] = Wout[i];
    if (tid < T_) bo[tid] = bout[tid];
    __syncthreads();

    int idx = blockIdx.x * 256 + tid;   // 0..32767
    const float4* h4 = (const float4*)(g_hseq + (size_t)idx * 512);
    float acc[T_];
#pragma unroll
    for (int t = 0; t < T_; t++) acc[t] = 0.f;

    for (int k4 = 0; k4 < 128; k4++) {
        float4 h = h4[k4];
#pragma unroll
        for (int t = 0; t < T_; t++) {
            float4 w = *(const float4*)&Wo[t * 512 + k4 * 4];
            acc[t] = fmaf(h.x, w.x, fmaf(h.y, w.y, fmaf(h.z, w.z, fmaf(h.w, w.w, acc[t]))));
        }
    }
#pragma unroll
    for (int t = 0; t < T_; t++)
        g_logits[(size_t)idx * T_ + t] = acc[t] + bo[t];
}

// ---------------------------------------------------------------------------
// Viterbi: one warp per batch. First-index argmax (strict >) matches
// jnp.argmax tie-breaking. Backpointers in smem.
// ---------------------------------------------------------------------------
__global__ __launch_bounds__(32) void viterbi_kernel(
    const float* __restrict__ trans, float* scores, float* paths)
{
    __shared__ float tr[T_ * T_];
    __shared__ float prev[T_];
    __shared__ unsigned char bps[(L_ - 1) * T_];

    int b = blockIdx.x;
    int j = threadIdx.x;

    for (int i = j; i < T_ * T_; i += 32) tr[i] = trans[i];
    if (j < T_) prev[j] = g_logits[(size_t)(b * L_) * T_ + j];
    __syncwarp();

    for (int t = 1; t < L_; t++) {
        float best = 0.f; int bp = 0;
        if (j < T_) {
            best = prev[0] + tr[j];
            bp = 0;
#pragma unroll
            for (int i = 1; i < T_; i++) {
                float v = prev[i] + tr[i * T_ + j];
                if (v > best) { best = v; bp = i; }
            }
        }
        __syncwarp();
        if (j < T_) {
            prev[j] = g_logits[(size_t)(b * L_ + t) * T_ + j] + best;
            bps[(t - 1) * T_ + j] = (unsigned char)bp;
        }
        __syncwarp();
    }

    if (j == 0) {
        float best = prev[0]; int tag = 0;
        for (int i = 1; i < T_; i++) if (prev[i] > best) { best = prev[i]; tag = i; }
        if (scores) scores[b] = best;
        if (paths) {
            paths[b * L_ + (L_ - 1)] = (float)tag;
            int st = tag;
            for (int t = L_ - 2; t >= 0; t--) {
                st = bps[t * T_ + st];
                paths[b * L_ + t] = (float)st;
            }
        }
    }
}

// ---------------------------------------------------------------------------
// Launcher
// ---------------------------------------------------------------------------
extern "C" void kernel_launch(void* const* d_in, const int* in_sizes, int n_in,
                              void* d_out, int out_size)
{
    const int*   sent  = (const int*)  d_in[0];
    const float* emb   = (const float*)d_in[1];
    const float* Wih_f = (const float*)d_in[2];
    const float* Whh_f = (const float*)d_in[3];
    const float* b_f   = (const float*)d_in[4];
    const float* Wih_b = (const float*)d_in[5];
    const float* Whh_b = (const float*)d_in[6];
    const float* b_b   = (const float*)d_in[7];
    const float* Wout  = (const float*)d_in[8];
    const float* bout  = (const float*)d_in[9];
    const float* trans = (const float*)d_in[10];
    const float* h0    = (const float*)d_in[11];
    const float* c0    = (const float*)d_in[12];

    float* out = (float*)d_out;
    float* scores = nullptr;
    float* paths  = nullptr;
    if (out_size >= B_ + B_ * L_)      { scores = out; paths = out + B_; }
    else if (out_size == B_ * L_)      { paths = out; }
    else                               { scores = out; }

    // 1. init h buffers + counters
    init_kernel<<<128, 256>>>(h0);

    // 2. fused embed + input projections (both directions), fp32x2
    dim3 gg(G4H / 64, M_ / 128, 2);   // (16, 256, 2)
    input_gemm_kernel<<<gg, 256>>>(sent, emb, Wih_f, b_f, Wih_b, b_b);

    // 3. persistent recurrence (128 co-resident blocks, ~146 KB smem each)
    const int smem_bytes = (128 * 260 + 8 * 260 + 128 * 9) * (int)sizeof(float);
    cudaFuncSetAttribute(lstm_kernel, cudaFuncAttributeMaxDynamicSharedMemorySize, smem_bytes);
    lstm_kernel<<<NBLK_LSTM, 256, smem_bytes>>>(c0, Whh_f, Whh_b);

    // 4. output projection
    logits_kernel<<<M_ / 256, 256>>>(Wout, bout);

    // 5. Viterbi decode + write outputs
    viterbi_kernel<<<B_, 32>>>(trans, scores, paths);
}

// round 10
// speedup vs baseline: 1.1545x; 1.1545x over previous
#include <cuda_runtime.h>
#include <math.h>

// Problem constants
#define B_   64
#define L_   512
#define D_   256
#define H_   256
#define T_   11
#define M_   (B_ * L_)      // 32768 rows (b*L + l)
#define G4H  (4 * H_)       // 1024 gate rows (i,f,g,o blocks of 256)

#define NBLK_LSTM 128       // persistent blocks (<=148 SMs, 1/SM)

// smem layout (floats)
#define OFF_W    0          // W_hh: 128 rows * 260
#define OFF_H    33280      // h: 8 * 260
#define OFF_G    35360      // G: 128 * 9
#define OFF_WS   36512      // producer W tiles: 2 * 16 * 132
#define OFF_ES   40736      // producer E tiles: 2 * 16 * 132
#define OFF_CNT  44960      // produced-group counter
#define SMEM_FLOATS 44964

#define BAR_C() asm volatile("bar.sync 1, 256;" ::: "memory")
#define BAR_P() asm volatile("bar.sync 2, 256;" ::: "memory")

// ---------------------------------------------------------------------------
// Scratch (static __device__ — no allocations allowed)
// ---------------------------------------------------------------------------
__device__ float g_gates[2 * 32768 * 1024];     // [dir][b*L+l][4H] input-proj + bias
__device__ float g_hseq[32768 * 512];           // [b*L+l][512] = concat(hf, hb)
__device__ float g_hbuf[2][2][B_ * H_];         // [dir][parity][b*H + j]
__device__ float g_logits[32768 * T_];          // [b*L+l][T]
__device__ unsigned int g_cnt[2][8];            // per-(dir, batch-group) h-completion

// ---------------------------------------------------------------------------
// Init: copy h0 into parity-0 h buffers, reset counters
// ---------------------------------------------------------------------------
__global__ void init_kernel(const float* __restrict__ h0) {
    int i = blockIdx.x * blockDim.x + threadIdx.x;
    if (i < 16) ((unsigned int*)g_cnt)[i] = 0u;
    if (i < 2 * B_ * H_) {
        int dir = i / (B_ * H_);
        int rem = i - dir * (B_ * H_);
        g_hbuf[dir][0][rem] = h0[i];
    }
}

// ---------------------------------------------------------------------------
// Fused persistent kernel: producer warps (0-7) compute the input projection
// for THIS block's private gate slice; compute warps (8-15) run the
// recurrence.  Producer->consumer sync is a block-local smem counter over
// 16-l groups.  Cross-block h exchange unchanged (global monotonic counters).
// ---------------------------------------------------------------------------
__global__ __launch_bounds__(512, 1) void lstm_kernel(
    const float* __restrict__ c0,
    const float* __restrict__ Whh_f, const float* __restrict__ Whh_b,
    const int* __restrict__ sent, const float* __restrict__ emb,
    const float* __restrict__ Wih_f, const float* __restrict__ b_f,
    const float* __restrict__ Wih_b, const float* __restrict__ b_b)
{
    extern __shared__ float sm[];
    float4* Wsm4 = (float4*)(sm + OFF_W);          // 128 rows * 65 float4 (pad)
    float4* hsm4 = (float4*)(sm + OFF_H);          // 8 batches * 65 float4
    float*  Gsm  = sm + OFF_G;                     // 128 rows * 9 (pad)
    float*  Ws   = sm + OFF_WS;                    // [buf][k=16][n=128 pad 132]
    float*  Es   = sm + OFF_ES;                    // [buf][k=16][m=128 pad 132]
    volatile unsigned int* prod = (volatile unsigned int*)(sm + OFF_CNT);

    const int tid = threadIdx.x;
    const int bid = blockIdx.x;
    const int dir = bid >> 6;
    const int sub = bid & 63;
    const int bg  = sub >> 3;              // batch group 0..7
    const int b0  = bg * 8;                // batch tile base
    const int j0  = (sub & 7) * 32;        // hidden tile base

    if (tid == 0) *prod = 0u;

    // Compute threads preload W_hh slice: smem row r -> gate g=r>>5, j0+(r&31)
    if (tid >= 256) {
        const int ctid = tid - 256;
        const float4* Wg4 = (const float4*)(dir ? Whh_b : Whh_f);
        for (int idx = ctid; idx < 128 * 64; idx += 256) {
            int r = idx >> 6, k4 = idx & 63;
            int g = r >> 5, jj = r & 31;
            Wsm4[r * 65 + k4] = Wg4[(size_t)(g * H_ + j0 + jj) * 64 + k4];
        }
    }
    __syncthreads();   // everyone: prod init + W_hh visible

    if (tid < 256) {
        // ================= PRODUCER (warps 0-7, low priority) =============
        const float* Wih  = dir ? Wih_b : Wih_f;
        const float* bias = dir ? b_b  : b_f;
        float* outBase = g_gates + (size_t)dir * M_ * G4H;

        const int n   = tid & 127;          // stage row id (gate-row / m index)
        const int kq  = tid >> 7;           // 0/1: which 8-k half this thread stages
        const int nt  = tid >> 4;           // 0..15: n-tile (8 rows)
        const int mt  = tid & 15;           // 0..15: m-tile (8 cols)

        const int gblk = n >> 5, jj = n & 31;
        const float* wRow = Wih + (size_t)(gblk * H_ + j0 + jj) * D_ + kq * 8;

        const int growN0 = (nt >> 2) * H_ + j0 + (nt & 3) * 8;   // first of 8 n-rows
        float bias8[8];
#pragma unroll
        for (int j = 0; j < 8; j++) bias8[j] = bias[growN0 + j];

        for (int g = 0; g < 32; g++) {
            const int lbase = (dir ? (31 - g) : g) * 16;

            // emb row for this thread's stage m (= n index): m -> (bi, li)
            const int sv = sent[(b0 + (n & 7)) * L_ + lbase + (n >> 3)];
            const float* eRow = emb + (size_t)sv * D_ + kq * 8;

            // Preload chunk 0 into buf 0
            {
                float4 w0 = *(const float4*)(wRow);
                float4 w1 = *(const float4*)(wRow + 4);
                float4 e0 = *(const float4*)(eRow);
                float4 e1 = *(const float4*)(eRow + 4);
                float* Wd = Ws + (kq * 8) * 132 + n;
                Wd[0*132]=w0.x; Wd[1*132]=w0.y; Wd[2*132]=w0.z; Wd[3*132]=w0.w;
                Wd[4*132]=w1.x; Wd[5*132]=w1.y; Wd[6*132]=w1.z; Wd[7*132]=w1.w;
                float* Ed = Es + (kq * 8) * 132 + n;
                Ed[0*132]=e0.x; Ed[1*132]=e0.y; Ed[2*132]=e0.z; Ed[3*132]=e0.w;
                Ed[4*132]=e1.x; Ed[5*132]=e1.y; Ed[6*132]=e1.z; Ed[7*132]=e1.w;
            }
            BAR_P();

            float acc[8][8];
#pragma unroll
            for (int i = 0; i < 8; i++)
#pragma unroll
                for (int j = 0; j < 8; j++) acc[i][j] = 0.f;

            for (int c = 0; c < 16; c++) {
                float4 nw0, nw1, ne0, ne1;
                if (c < 15) {
                    nw0 = *(const float4*)(wRow + (c + 1) * 16);
                    nw1 = *(const float4*)(wRow + (c + 1) * 16 + 4);
                    ne0 = *(const float4*)(eRow + (c + 1) * 16);
                    ne1 = *(const float4*)(eRow + (c + 1) * 16 + 4);
                }
                const float* Wb = Ws + (c & 1) * 2112;
                const float* Eb = Es + (c & 1) * 2112;
#pragma unroll
                for (int k = 0; k < 16; k++) {
                    float4 a0 = *(const float4*)(Wb + k * 132 + nt * 8);
                    float4 a1 = *(const float4*)(Wb + k * 132 + nt * 8 + 4);
                    float4 bb0 = *(const float4*)(Eb + k * 132 + mt * 8);
                    float4 bb1 = *(const float4*)(Eb + k * 132 + mt * 8 + 4);
                    float wv[8] = {a0.x,a0.y,a0.z,a0.w,a1.x,a1.y,a1.z,a1.w};
                    float ev[8] = {bb0.x,bb0.y,bb0.z,bb0.w,bb1.x,bb1.y,bb1.z,bb1.w};
#pragma unroll
                    for (int i = 0; i < 8; i++)
#pragma unroll
                        for (int j = 0; j < 8; j++)
                            acc[i][j] = fmaf(wv[i], ev[j], acc[i][j]);
                }
                if (c < 15) {
                    float* Wd = Ws + ((c + 1) & 1) * 2112 + (kq * 8) * 132 + n;
                    Wd[0*132]=nw0.x; Wd[1*132]=nw0.y; Wd[2*132]=nw0.z; Wd[3*132]=nw0.w;
                    Wd[4*132]=nw1.x; Wd[5*132]=nw1.y; Wd[6*132]=nw1.z; Wd[7*132]=nw1.w;
                    float* Ed = Es + ((c + 1) & 1) * 2112 + (kq * 8) * 132 + n;
                    Ed[0*132]=ne0.x; Ed[1*132]=ne0.y; Ed[2*132]=ne0.z; Ed[3*132]=ne0.w;
                    Ed[4*132]=ne1.x; Ed[5*132]=ne1.y; Ed[6*132]=ne1.z; Ed[7*132]=ne1.w;
                }
                BAR_P();
            }

            // Write out 8 m columns (each 8 consecutive gate rows)
#pragma unroll
            for (int j = 0; j < 8; j++) {
                int m = mt * 8 + j;
                int bi = m & 7, li = m >> 3;
                float* dst = outBase +
                    ((size_t)(b0 + bi) * L_ + (lbase + li)) * G4H + growN0;
                float4 o0 = make_float4(acc[0][j] + bias8[0], acc[1][j] + bias8[1],
                                        acc[2][j] + bias8[2], acc[3][j] + bias8[3]);
                float4 o1 = make_float4(acc[4][j] + bias8[4], acc[5][j] + bias8[5],
                                        acc[6][j] + bias8[6], acc[7][j] + bias8[7]);
                __stcg((float4*)dst, o0);
                __stcg((float4*)(dst + 4), o1);
            }
            __threadfence();      // my gate stores visible before counter bump
            BAR_P();              // all producers done with this group
            if (tid == 0) *prod = (unsigned)(g + 1);
        }
        return;   // producers exit; compute warps continue alone
    }

    // ================= COMPUTE (warps 8-15, high priority) ================
    const int ctid = tid - 256;

    // Cell-update thread mapping
    const int ub = ctid >> 5, ujj = ctid & 31;
    float c = c0[dir * B_ * H_ + (b0 + ub) * H_ + j0 + ujj];

    // GEMM thread mapping (R7): 8-way interleaved k-split
    const int ks   = ctid & 7;
    const int tile = ctid >> 3;
    const int rt   = tile >> 1;            // 0..15 -> rows rt*8..rt*8+7
    const int bq   = tile & 1;             // batches bq*4..bq*4+3
    const int ri_fin = ((ks & 1) << 2) | (ks & 2) | ((ks >> 2) & 1);
    const int row_fin = rt * 8 + ri_fin;
    const int grow_fin = (row_fin >> 5) * H_ + j0 + (row_fin & 31);

    const float* gatesD = g_gates + (size_t)dir * M_ * G4H;
    volatile unsigned int* cnt = &g_cnt[dir][bg];

    for (int t = 0; t < L_; t++) {
        const int l  = dir ? (L_ - 1 - t) : t;
        const float* hread  = g_hbuf[dir][t & 1];
        float*       hwrite = g_hbuf[dir][(t & 1) ^ 1];

        // Wait for producer group covering this l (same formula both dirs)
        {
            const unsigned need = (unsigned)(t >> 4) + 1u;
            while (*prod < need) { __nanosleep(20); }
        }

        // Prefetch input-projection preacts — in flight during h wait
        float gi[4];
#pragma unroll
        for (int bi = 0; bi < 4; bi++)
            gi[bi] = gatesD[(size_t)((b0 + bq * 4 + bi) * L_ + l) * G4H + grow_fin];

        // Wait for the 8 h-producers of this batch group (prev step)
        if (t > 0) {
            const unsigned int need = 8u * (unsigned)t;
            while (*cnt < need) { __nanosleep(20); }
        }

        // Stage previous h (8 batches x 256 units); L2-coherent loads
        const float4* hr4 = (const float4*)hread;
        for (int i = ctid; i < 8 * 64; i += 256) {
            int r = i >> 6, c4 = i & 63;
            hsm4[r * 65 + c4] = __ldcg(&hr4[(b0 + r) * 64 + c4]);
        }
        BAR_C();

        // 8x4 register-tiled GEMM, interleaved k-split (k4 = ks + 8*kk)
        float acc[32];
#pragma unroll
        for (int v = 0; v < 32; v++) acc[v] = 0.f;

#pragma unroll 2
        for (int kk = 0; kk < 8; kk++) {
            const int k4 = ks + kk * 8;
            float4 hv[4];
#pragma unroll
            for (int bi = 0; bi < 4; bi++)
                hv[bi] = hsm4[(bq * 4 + bi) * 65 + k4];
#pragma unroll
            for (int ri = 0; ri < 8; ri++) {
                float4 w = Wsm4[(rt * 8 + ri) * 65 + k4];
#pragma unroll
                for (int bi = 0; bi < 4; bi++) {
                    float a = acc[ri * 4 + bi];
                    a = fmaf(w.x, hv[bi].x, a);
                    a = fmaf(w.y, hv[bi].y, a);
                    a = fmaf(w.z, hv[bi].z, a);
                    a = fmaf(w.w, hv[bi].w, a);
                    acc[ri * 4 + bi] = a;
                }
            }
        }

        // K-split reduction: 3 butterfly rounds over lane bits 0..2 (ks)
#pragma unroll
        for (int s = 0; s < 3; s++) {
            const int half = 16 >> s;              // 16, 8, 4
            const bool up = (ks >> s) & 1;
#pragma unroll
            for (int i = 0; i < half; i++) {
                float send = up ? acc[i] : acc[i + half];
                float recv = __shfl_xor_sync(0xffffffffu, send, 1 << s);
                acc[i] = (up ? acc[i + half] : acc[i]) + recv;
            }
        }
#pragma unroll
        for (int bi = 0; bi < 4; bi++)
            Gsm[row_fin * 9 + bq * 4 + bi] = acc[bi] + gi[bi];
        BAR_C();

        // Gate nonlinearity + state update (PyTorch order i,f,g,o)
        float iv = Gsm[( 0 + ujj) * 9 + ub];
        float fv = Gsm[(32 + ujj) * 9 + ub];
        float gv = Gsm[(64 + ujj) * 9 + ub];
        float ov = Gsm[(96 + ujj) * 9 + ub];
        float si = __fdividef(1.f, 1.f + __expf(-iv));
        float sf = __fdividef(1.f, 1.f + __expf(-fv));
        float so = __fdividef(1.f, 1.f + __expf(-ov));
        c = sf * c + si * tanhf(gv);
        float h = so * tanhf(c);

        int bglob = b0 + ub;
        __stcg(&hwrite[bglob * H_ + j0 + ujj], h);
        __stcg(&g_hseq[(size_t)(bglob * L_ + l) * 512 + dir * H_ + j0 + ujj], h);

        // Publish: all h stores done -> bump group counter
        BAR_C();
        if (ctid == 0) {
            __threadfence();
            atomicAdd(&g_cnt[dir][bg], 1u);
        }
    }
}

// ---------------------------------------------------------------------------
// Output projection: logits[m][t] = hseq[m] . W_out[t] + b_out[t]
// ---------------------------------------------------------------------------
__global__ __launch_bounds__(256) void logits_kernel(
    const float* __restrict__ Wout, const float* __restrict__ bout)
{
    __shared__ float Wo[T_ * 512];
    __shared__ float bo[T_];
    int tid = threadIdx.x;
    for (int i = tid; i < T_ * 512; i += 256) Wo[i] = Wout[i];
    if (tid < T_) bo[tid] = bout[tid];
    __syncthreads();

    int idx = blockIdx.x * 256 + tid;   // 0..32767
    const float4* h4 = (const float4*)(g_hseq + (size_t)idx * 512);
    float acc[T_];
#pragma unroll
    for (int t = 0; t < T_; t++) acc[t] = 0.f;

    for (int k4 = 0; k4 < 128; k4++) {
        float4 h = h4[k4];
#pragma unroll
        for (int t = 0; t < T_; t++) {
            float4 w = *(const float4*)&Wo[t * 512 + k4 * 4];
            acc[t] = fmaf(h.x, w.x, fmaf(h.y, w.y, fmaf(h.z, w.z, fmaf(h.w, w.w, acc[t]))));
        }
    }
#pragma unroll
    for (int t = 0; t < T_; t++)
        g_logits[(size_t)idx * T_ + t] = acc[t] + bo[t];
}

// ---------------------------------------------------------------------------
// Viterbi: one warp per batch. First-index argmax (strict >) matches
// jnp.argmax tie-breaking. Backpointers in smem.
// ---------------------------------------------------------------------------
__global__ __launch_bounds__(32) void viterbi_kernel(
    const float* __restrict__ trans, float* scores, float* paths)
{
    __shared__ float tr[T_ * T_];
    __shared__ float prev[T_];
    __shared__ unsigned char bps[(L_ - 1) * T_];

    int b = blockIdx.x;
    int j = threadIdx.x;

    for (int i = j; i < T_ * T_; i += 32) tr[i] = trans[i];
    if (j < T_) prev[j] = g_logits[(size_t)(b * L_) * T_ + j];
    __syncwarp();

    for (int t = 1; t < L_; t++) {
        float best = 0.f; int bp = 0;
        if (j < T_) {
            best = prev[0] + tr[j];
            bp = 0;
#pragma unroll
            for (int i = 1; i < T_; i++) {
                float v = prev[i] + tr[i * T_ + j];
                if (v > best) { best = v; bp = i; }
            }
        }
        __syncwarp();
        if (j < T_) {
            prev[j] = g_logits[(size_t)(b * L_ + t) * T_ + j] + best;
            bps[(t - 1) * T_ + j] = (unsigned char)bp;
        }
        __syncwarp();
    }

    if (j == 0) {
        float best = prev[0]; int tag = 0;
        for (int i = 1; i < T_; i++) if (prev[i] > best) { best = prev[i]; tag = i; }
        if (scores) scores[b] = best;
        if (paths) {
            paths[b * L_ + (L_ - 1)] = (float)tag;
            int st = tag;
            for (int t = L_ - 2; t >= 0; t--) {
                st = bps[t * T_ + st];
                paths[b * L_ + t] = (float)st;
            }
        }
    }
}

// ---------------------------------------------------------------------------
// Launcher
// ---------------------------------------------------------------------------
extern "C" void kernel_launch(void* const* d_in, const int* in_sizes, int n_in,
                              void* d_out, int out_size)
{
    const int*   sent  = (const int*)  d_in[0];
    const float* emb   = (const float*)d_in[1];
    const float* Wih_f = (const float*)d_in[2];
    const float* Whh_f = (const float*)d_in[3];
    const float* b_f   = (const float*)d_in[4];
    const float* Wih_b = (const float*)d_in[5];
    const float* Whh_b = (const float*)d_in[6];
    const float* b_b   = (const float*)d_in[7];
    const float* Wout  = (const float*)d_in[8];
    const float* bout  = (const float*)d_in[9];
    const float* trans = (const float*)d_in[10];
    const float* h0    = (const float*)d_in[11];
    const float* c0    = (const float*)d_in[12];

    float* out = (float*)d_out;
    float* scores = nullptr;
    float* paths  = nullptr;
    if (out_size >= B_ + B_ * L_)      { scores = out; paths = out + B_; }
    else if (out_size == B_ * L_)      { paths = out; }
    else                               { scores = out; }

    // 1. init h buffers + counters
    init_kernel<<<128, 256>>>(h0);

    // 2. fused producer + recurrence (128 co-resident blocks, ~176 KB smem)
    const int smem_bytes = SMEM_FLOATS * (int)sizeof(float);
    cudaFuncSetAttribute(lstm_kernel, cudaFuncAttributeMaxDynamicSharedMemorySize, smem_bytes);
    lstm_kernel<<<NBLK_LSTM, 512, smem_bytes>>>(c0, Whh_f, Whh_b,
                                                sent, emb, Wih_f, b_f, Wih_b, b_b);

    // 3. output projection
    logits_kernel<<<M_ / 256, 256>>>(Wout, bout);

    // 4. Viterbi decode + write outputs
    viterbi_kernel<<<B_, 32>>>(trans, scores, paths);
}

// round 11
// speedup vs baseline: 1.2021x; 1.0412x over previous
#include <cuda_runtime.h>
#include <math.h>

// Problem constants
#define B_   64
#define L_   512
#define D_   256
#define H_   256
#define T_   11
#define M_   (B_ * L_)      // 32768 rows (b*L + l)
#define G4H  (4 * H_)       // 1024 gate rows (i,f,g,o blocks of 256)

#define NBLK_LSTM 128       // persistent blocks (<=148 SMs, 1/SM)

// smem layout (floats)
#define OFF_W    0          // W_hh: 128 rows * 260
#define OFF_H    33280      // h: 8 * 260
#define OFF_G    35360      // G: 128 * 9
#define OFF_WS   36512      // producer W tiles: 2 * 16 * 132
#define OFF_ES   40736      // producer E tiles: 2 * 16 * 132
#define OFF_CNT  44960      // produced-group counter
#define SMEM_FLOATS 44964

#define BAR_C() asm volatile("bar.sync 1, 256;" ::: "memory")
#define BAR_P() asm volatile("bar.sync 2, 256;" ::: "memory")

// ---------------------------------------------------------------------------
// Scratch (static __device__ — no allocations allowed)
// ---------------------------------------------------------------------------
__device__ float g_gates[2 * 32768 * 1024];     // [dir][b*L+l][4H] input-proj + bias
__device__ float g_hseq[32768 * 512];           // [b*L+l][512] = concat(hf, hb)
__device__ float g_hbuf[2][2][B_ * H_];         // [dir][parity][b*H + j]
__device__ float g_logits[32768 * T_];          // [b*L+l][T]
__device__ unsigned int g_cnt[2][8];            // per-(dir, batch-group) h-completion

// ---------------------------------------------------------------------------
// Init: copy h0 into parity-0 h buffers, reset counters
// ---------------------------------------------------------------------------
__global__ void init_kernel(const float* __restrict__ h0) {
    int i = blockIdx.x * blockDim.x + threadIdx.x;
    if (i < 16) ((unsigned int*)g_cnt)[i] = 0u;
    if (i < 2 * B_ * H_) {
        int dir = i / (B_ * H_);
        int rem = i - dir * (B_ * H_);
        g_hbuf[dir][0][rem] = h0[i];
    }
}

// ---------------------------------------------------------------------------
// Fused persistent kernel: producer warps (0-7) compute the input projection
// for THIS block's private gate slice; compute warps (8-15) run the
// recurrence.  Producer->consumer sync is a block-local smem counter over
// 16-l groups.  Cross-block h exchange unchanged (global monotonic counters).
// ---------------------------------------------------------------------------
__global__ __launch_bounds__(512, 1) void lstm_kernel(
    const float* __restrict__ c0,
    const float* __restrict__ Whh_f, const float* __restrict__ Whh_b,
    const int* __restrict__ sent, const float* __restrict__ emb,
    const float* __restrict__ Wih_f, const float* __restrict__ b_f,
    const float* __restrict__ Wih_b, const float* __restrict__ b_b)
{
    extern __shared__ float sm[];
    float4* Wsm4 = (float4*)(sm + OFF_W);          // 128 rows * 65 float4 (pad)
    float4* hsm4 = (float4*)(sm + OFF_H);          // 8 batches * 65 float4
    float*  Gsm  = sm + OFF_G;                     // 128 rows * 9 (pad)
    float*  Ws   = sm + OFF_WS;                    // [buf][k=16][n=128 pad 132]
    float*  Es   = sm + OFF_ES;                    // [buf][k=16][m=128 pad 132]
    volatile unsigned int* prod = (volatile unsigned int*)(sm + OFF_CNT);

    const int tid = threadIdx.x;
    const int bid = blockIdx.x;
    const int dir = bid >> 6;
    const int sub = bid & 63;
    const int bg  = sub >> 3;              // batch group 0..7
    const int b0  = bg * 8;                // batch tile base
    const int j0  = (sub & 7) * 32;        // hidden tile base

    if (tid == 0) *prod = 0u;

    // Compute threads preload W_hh slice: smem row r -> gate g=r>>5, j0+(r&31)
    if (tid >= 256) {
        const int ctid = tid - 256;
        const float4* Wg4 = (const float4*)(dir ? Whh_b : Whh_f);
        for (int idx = ctid; idx < 128 * 64; idx += 256) {
            int r = idx >> 6, k4 = idx & 63;
            int g = r >> 5, jj = r & 31;
            Wsm4[r * 65 + k4] = Wg4[(size_t)(g * H_ + j0 + jj) * 64 + k4];
        }
    }
    __syncthreads();   // everyone: prod init + W_hh visible

    if (tid < 256) {
        // ================= PRODUCER (warps 0-7, low priority) =============
        const float* Wih  = dir ? Wih_b : Wih_f;
        const float* bias = dir ? b_b  : b_f;
        float* outBase = g_gates + (size_t)dir * M_ * G4H;

        const int n   = tid & 127;          // stage row id (gate-row / m index)
        const int kq  = tid >> 7;           // 0/1: which 8-k half this thread stages
        const int nt  = tid >> 4;           // 0..15: n-tile (8 rows)
        const int mt  = tid & 15;           // 0..15: m-tile (8 cols)

        const int gblk = n >> 5, jj = n & 31;
        const float* wRow = Wih + (size_t)(gblk * H_ + j0 + jj) * D_ + kq * 8;

        const int growN0 = (nt >> 2) * H_ + j0 + (nt & 3) * 8;   // first of 8 n-rows
        float bias8[8];
#pragma unroll
        for (int j = 0; j < 8; j++) bias8[j] = bias[growN0 + j];

        for (int g = 0; g < 32; g++) {
            const int lbase = (dir ? (31 - g) : g) * 16;

            // emb row for this thread's stage m (= n index): m -> (bi, li)
            const int sv = sent[(b0 + (n & 7)) * L_ + lbase + (n >> 3)];
            const float* eRow = emb + (size_t)sv * D_ + kq * 8;

            // Preload chunk 0 into buf 0
            {
                float4 w0 = *(const float4*)(wRow);
                float4 w1 = *(const float4*)(wRow + 4);
                float4 e0 = *(const float4*)(eRow);
                float4 e1 = *(const float4*)(eRow + 4);
                float* Wd = Ws + (kq * 8) * 132 + n;
                Wd[0*132]=w0.x; Wd[1*132]=w0.y; Wd[2*132]=w0.z; Wd[3*132]=w0.w;
                Wd[4*132]=w1.x; Wd[5*132]=w1.y; Wd[6*132]=w1.z; Wd[7*132]=w1.w;
                float* Ed = Es + (kq * 8) * 132 + n;
                Ed[0*132]=e0.x; Ed[1*132]=e0.y; Ed[2*132]=e0.z; Ed[3*132]=e0.w;
                Ed[4*132]=e1.x; Ed[5*132]=e1.y; Ed[6*132]=e1.z; Ed[7*132]=e1.w;
            }
            BAR_P();

            float acc[8][8];
#pragma unroll
            for (int i = 0; i < 8; i++)
#pragma unroll
                for (int j = 0; j < 8; j++) acc[i][j] = 0.f;

            for (int c = 0; c < 16; c++) {
                float4 nw0, nw1, ne0, ne1;
                if (c < 15) {
                    nw0 = *(const float4*)(wRow + (c + 1) * 16);
                    nw1 = *(const float4*)(wRow + (c + 1) * 16 + 4);
                    ne0 = *(const float4*)(eRow + (c + 1) * 16);
                    ne1 = *(const float4*)(eRow + (c + 1) * 16 + 4);
                }
                const float* Wb = Ws + (c & 1) * 2112;
                const float* Eb = Es + (c & 1) * 2112;
#pragma unroll
                for (int k = 0; k < 16; k++) {
                    float4 a0 = *(const float4*)(Wb + k * 132 + nt * 8);
                    float4 a1 = *(const float4*)(Wb + k * 132 + nt * 8 + 4);
                    float4 bb0 = *(const float4*)(Eb + k * 132 + mt * 8);
                    float4 bb1 = *(const float4*)(Eb + k * 132 + mt * 8 + 4);
                    float wv[8] = {a0.x,a0.y,a0.z,a0.w,a1.x,a1.y,a1.z,a1.w};
                    float ev[8] = {bb0.x,bb0.y,bb0.z,bb0.w,bb1.x,bb1.y,bb1.z,bb1.w};
#pragma unroll
                    for (int i = 0; i < 8; i++)
#pragma unroll
                        for (int j = 0; j < 8; j++)
                            acc[i][j] = fmaf(wv[i], ev[j], acc[i][j]);
                }
                if (c < 15) {
                    float* Wd = Ws + ((c + 1) & 1) * 2112 + (kq * 8) * 132 + n;
                    Wd[0*132]=nw0.x; Wd[1*132]=nw0.y; Wd[2*132]=nw0.z; Wd[3*132]=nw0.w;
                    Wd[4*132]=nw1.x; Wd[5*132]=nw1.y; Wd[6*132]=nw1.z; Wd[7*132]=nw1.w;
                    float* Ed = Es + ((c + 1) & 1) * 2112 + (kq * 8) * 132 + n;
                    Ed[0*132]=ne0.x; Ed[1*132]=ne0.y; Ed[2*132]=ne0.z; Ed[3*132]=ne0.w;
                    Ed[4*132]=ne1.x; Ed[5*132]=ne1.y; Ed[6*132]=ne1.z; Ed[7*132]=ne1.w;
                }
                BAR_P();
            }

            // Write out 8 m columns (each 8 consecutive gate rows)
#pragma unroll
            for (int j = 0; j < 8; j++) {
                int m = mt * 8 + j;
                int bi = m & 7, li = m >> 3;
                float* dst = outBase +
                    ((size_t)(b0 + bi) * L_ + (lbase + li)) * G4H + growN0;
                float4 o0 = make_float4(acc[0][j] + bias8[0], acc[1][j] + bias8[1],
                                        acc[2][j] + bias8[2], acc[3][j] + bias8[3]);
                float4 o1 = make_float4(acc[4][j] + bias8[4], acc[5][j] + bias8[5],
                                        acc[6][j] + bias8[6], acc[7][j] + bias8[7]);
                __stcg((float4*)dst, o0);
                __stcg((float4*)(dst + 4), o1);
            }
            __threadfence();      // my gate stores visible before counter bump
            BAR_P();              // all producers done with this group
            if (tid == 0) *prod = (unsigned)(g + 1);
        }
        return;   // producers exit; compute warps continue alone
    }

    // ================= COMPUTE (warps 8-15, high priority) ================
    const int ctid = tid - 256;

    // Cell-update thread mapping
    const int ub = ctid >> 5, ujj = ctid & 31;
    float c = c0[dir * B_ * H_ + (b0 + ub) * H_ + j0 + ujj];

    // GEMM thread mapping (R7): 8-way interleaved k-split
    const int ks   = ctid & 7;
    const int tile = ctid >> 3;
    const int rt   = tile >> 1;            // 0..15 -> rows rt*8..rt*8+7
    const int bq   = tile & 1;             // batches bq*4..bq*4+3
    const int ri_fin = ((ks & 1) << 2) | (ks & 2) | ((ks >> 2) & 1);
    const int row_fin = rt * 8 + ri_fin;
    const int grow_fin = (row_fin >> 5) * H_ + j0 + (row_fin & 31);

    const float* gatesD = g_gates + (size_t)dir * M_ * G4H;
    volatile unsigned int* cnt = &g_cnt[dir][bg];

    for (int t = 0; t < L_; t++) {
        const int l  = dir ? (L_ - 1 - t) : t;
        const float* hread  = g_hbuf[dir][t & 1];
        float*       hwrite = g_hbuf[dir][(t & 1) ^ 1];

        // Wait for producer group covering this l (same formula both dirs)
        {
            const unsigned need = (unsigned)(t >> 4) + 1u;
            while (*prod < need) { __nanosleep(20); }
        }

        // Prefetch input-projection preacts — in flight during h wait
        float gi[4];
#pragma unroll
        for (int bi = 0; bi < 4; bi++)
            gi[bi] = gatesD[(size_t)((b0 + bq * 4 + bi) * L_ + l) * G4H + grow_fin];

        // Wait for the 8 h-producers of this batch group (prev step)
        if (t > 0) {
            const unsigned int need = 8u * (unsigned)t;
            while (*cnt < need) { __nanosleep(20); }
        }

        // Stage previous h (8 batches x 256 units); L2-coherent loads
        const float4* hr4 = (const float4*)hread;
        for (int i = ctid; i < 8 * 64; i += 256) {
            int r = i >> 6, c4 = i & 63;
            hsm4[r * 65 + c4] = __ldcg(&hr4[(b0 + r) * 64 + c4]);
        }
        BAR_C();

        // 8x4 register-tiled GEMM, interleaved k-split (k4 = ks + 8*kk)
        float acc[32];
#pragma unroll
        for (int v = 0; v < 32; v++) acc[v] = 0.f;

#pragma unroll 2
        for (int kk = 0; kk < 8; kk++) {
            const int k4 = ks + kk * 8;
            float4 hv[4];
#pragma unroll
            for (int bi = 0; bi < 4; bi++)
                hv[bi] = hsm4[(bq * 4 + bi) * 65 + k4];
#pragma unroll
            for (int ri = 0; ri < 8; ri++) {
                float4 w = Wsm4[(rt * 8 + ri) * 65 + k4];
#pragma unroll
                for (int bi = 0; bi < 4; bi++) {
                    float a = acc[ri * 4 + bi];
                    a = fmaf(w.x, hv[bi].x, a);
                    a = fmaf(w.y, hv[bi].y, a);
                    a = fmaf(w.z, hv[bi].z, a);
                    a = fmaf(w.w, hv[bi].w, a);
                    acc[ri * 4 + bi] = a;
                }
            }
        }

        // K-split reduction: 3 butterfly rounds over lane bits 0..2 (ks)
#pragma unroll
        for (int s = 0; s < 3; s++) {
            const int half = 16 >> s;              // 16, 8, 4
            const bool up = (ks >> s) & 1;
#pragma unroll
            for (int i = 0; i < half; i++) {
                float send = up ? acc[i] : acc[i + half];
                float recv = __shfl_xor_sync(0xffffffffu, send, 1 << s);
                acc[i] = (up ? acc[i + half] : acc[i]) + recv;
            }
        }
#pragma unroll
        for (int bi = 0; bi < 4; bi++)
            Gsm[row_fin * 9 + bq * 4 + bi] = acc[bi] + gi[bi];
        BAR_C();

        // Gate nonlinearity + state update (PyTorch order i,f,g,o)
        float iv = Gsm[( 0 + ujj) * 9 + ub];
        float fv = Gsm[(32 + ujj) * 9 + ub];
        float gv = Gsm[(64 + ujj) * 9 + ub];
        float ov = Gsm[(96 + ujj) * 9 + ub];
        float si = __fdividef(1.f, 1.f + __expf(-iv));
        float sf = __fdividef(1.f, 1.f + __expf(-fv));
        float so = __fdividef(1.f, 1.f + __expf(-ov));
        c = sf * c + si * tanhf(gv);
        float h = so * tanhf(c);

        int bglob = b0 + ub;
        __stcg(&hwrite[bglob * H_ + j0 + ujj], h);
        __stcg(&g_hseq[(size_t)(bglob * L_ + l) * 512 + dir * H_ + j0 + ujj], h);

        // Publish: all h stores done -> bump group counter
        BAR_C();
        if (ctid == 0) {
            __threadfence();
            atomicAdd(&g_cnt[dir][bg], 1u);
        }
    }
}

// ---------------------------------------------------------------------------
// Output projection: logits[m][t] = hseq[m] . W_out[t] + b_out[t]
// ---------------------------------------------------------------------------
__global__ __launch_bounds__(256) void logits_kernel(
    const float* __restrict__ Wout, const float* __restrict__ bout)
{
    __shared__ float Wo[T_ * 512];
    __shared__ float bo[T_];
    int tid = threadIdx.x;
    for (int i = tid; i < T_ * 512; i += 256) Wo[i] = Wout[i];
    if (tid < T_) bo[tid] = bout[tid];
    __syncthreads();

    int idx = blockIdx.x * 256 + tid;   // 0..32767
    const float4* h4 = (const float4*)(g_hseq + (size_t)idx * 512);
    float acc[T_];
#pragma unroll
    for (int t = 0; t < T_; t++) acc[t] = 0.f;

    for (int k4 = 0; k4 < 128; k4++) {
        float4 h = h4[k4];
#pragma unroll
        for (int t = 0; t < T_; t++) {
            float4 w = *(const float4*)&Wo[t * 512 + k4 * 4];
            acc[t] = fmaf(h.x, w.x, fmaf(h.y, w.y, fmaf(h.z, w.z, fmaf(h.w, w.w, acc[t]))));
        }
    }
#pragma unroll
    for (int t = 0; t < T_; t++)
        g_logits[(size_t)idx * T_ + t] = acc[t] + bo[t];
}

// ---------------------------------------------------------------------------
// Viterbi: one warp per batch.  Register/shuffle hot loop:
//  - prev[] lives in a register per lane (lane j = tag j); gathers via shfl
//  - trans column tr[i][j] preloaded into 11 registers per lane
//  - all 512*11 logits preloaded into smem (coalesced) up-front
//  - 11-way argmax as a depth-4 pairwise tree; left wins on ties at every
//    node => global first-index semantics (matches jnp.argmax) exactly
// ---------------------------------------------------------------------------
__global__ __launch_bounds__(32) void viterbi_kernel(
    const float* __restrict__ trans, float* scores, float* paths)
{
    __shared__ float lg[L_ * T_];                  // 22.5 KB
    __shared__ unsigned char bps[(L_ - 1) * T_];

    const int b = blockIdx.x;
    const int j = threadIdx.x;

    // Preload this batch's logits (coalesced across the warp)
    const float* src = g_logits + (size_t)b * L_ * T_;
    for (int i = j; i < L_ * T_; i += 32) lg[i] = src[i];

    // trans column into registers: trC[i] = trans[i][j]
    const int jj = (j < T_) ? j : 0;
    float trC[T_];
#pragma unroll
    for (int i = 0; i < T_; i++) trC[i] = trans[i * T_ + jj];

    __syncwarp();
    float prev = (j < T_) ? lg[j] : -1e30f;

    for (int t = 1; t < L_; t++) {
        // Gather candidates: v[i] = prev(lane i) + trans[i][j]
        float v[T_];
#pragma unroll
        for (int i = 0; i < T_; i++)
            v[i] = __shfl_sync(0xffffffffu, prev, i) + trC[i];

        // Pairwise argmax tree, first index wins on ties (strict > to move)
        float mv[6]; int mi[6];
#pragma unroll
        for (int p = 0; p < 5; p++) {
            bool sel = v[2 * p + 1] > v[2 * p];
            mv[p] = sel ? v[2 * p + 1] : v[2 * p];
            mi[p] = sel ? 2 * p + 1 : 2 * p;
        }
        mv[5] = v[10]; mi[5] = 10;
        float nv[3]; int ni[3];
#pragma unroll
        for (int p = 0; p < 3; p++) {
            bool sel = mv[2 * p + 1] > mv[2 * p];
            nv[p] = sel ? mv[2 * p + 1] : mv[2 * p];
            ni[p] = sel ? mi[2 * p + 1] : mi[2 * p];
        }
        bool s01 = nv[1] > nv[0];
        float pv = s01 ? nv[1] : nv[0];
        int   pi = s01 ? ni[1] : ni[0];
        bool sf_ = nv[2] > pv;
        float best = sf_ ? nv[2] : pv;
        int   bp   = sf_ ? ni[2] : pi;

        prev = lg[t * T_ + jj] + best;      // jj==j for active lanes
        if (j < T_) bps[(t - 1) * T_ + j] = (unsigned char)bp;
    }

    __syncwarp();
    if (j == 0) {
        // Final argmax over lanes 0..10 (first index wins)
        float best = prev; int tag = 0;
#pragma unroll
        for (int i = 1; i < T_; i++) {
            float vi = __shfl_sync(0x7ffu, prev, i);
            if (vi > best) { best = vi; tag = i; }
        }
        if (scores) scores[b] = best;
        if (paths) {
            paths[b * L_ + (L_ - 1)] = (float)tag;
            int st = tag;
            for (int t = L_ - 2; t >= 0; t--) {
                st = bps[t * T_ + st];
                paths[b * L_ + t] = (float)st;
            }
        }
    } else if (j < T_) {
        // participate in the shuffles above
#pragma unroll
        for (int i = 1; i < T_; i++) __shfl_sync(0x7ffu, prev, i);
    }
}

// ---------------------------------------------------------------------------
// Launcher
// ---------------------------------------------------------------------------
extern "C" void kernel_launch(void* const* d_in, const int* in_sizes, int n_in,
                              void* d_out, int out_size)
{
    const int*   sent  = (const int*)  d_in[0];
    const float* emb   = (const float*)d_in[1];
    const float* Wih_f = (const float*)d_in[2];
    const float* Whh_f = (const float*)d_in[3];
    const float* b_f   = (const float*)d_in[4];
    const float* Wih_b = (const float*)d_in[5];
    const float* Whh_b = (const float*)d_in[6];
    const float* b_b   = (const float*)d_in[7];
    const float* Wout  = (const float*)d_in[8];
    const float* bout  = (const float*)d_in[9];
    const float* trans = (const float*)d_in[10];
    const float* h0    = (const float*)d_in[11];
    const float* c0    = (const float*)d_in[12];

    float* out = (float*)d_out;
    float* scores = nullptr;
    float* paths  = nullptr;
    if (out_size >= B_ + B_ * L_)      { scores = out; paths = out + B_; }
    else if (out_size == B_ * L_)      { paths = out; }
    else                               { scores = out; }

    // 1. init h buffers + counters
    init_kernel<<<128, 256>>>(h0);

    // 2. fused producer + recurrence (128 co-resident blocks, ~176 KB smem)
    const int smem_bytes = SMEM_FLOATS * (int)sizeof(float);
    cudaFuncSetAttribute(lstm_kernel, cudaFuncAttributeMaxDynamicSharedMemorySize, smem_bytes);
    lstm_kernel<<<NBLK_LSTM, 512, smem_bytes>>>(c0, Whh_f, Whh_b,
                                                sent, emb, Wih_f, b_f, Wih_b, b_b);

    // 3. output projection
    logits_kernel<<<M_ / 256, 256>>>(Wout, bout);

    // 4. Viterbi decode + write outputs
    viterbi_kernel<<<B_, 32>>>(trans, scores, paths);
}